// round 2
// baseline (speedup 1.0000x reference)
#include <cuda_runtime.h>
#include <cuda_bf16.h>

#define N_NODES  100000
#define N_EDGES  1600000
#define N_GRAPHS 64

// ---------------- scratch (device globals; no allocation allowed) ----------
__device__ __align__(256) float g_x1   [N_NODES * 8];   // n_feat * inv_sqrt_out
__device__ __align__(256) float g_agg1 [N_NODES * 8];
__device__ __align__(256) float g_h1s  [N_NODES * 16];  // relu(h1) * inv_sqrt_out
__device__ __align__(256) float g_agg2 [N_NODES * 16];
__device__ __align__(256) float g_z3   [N_NODES * 12];  // (h2*invout)@W3, stride 12 (10 used)
__device__ __align__(256) float g_agg3 [N_NODES * 12];
__device__ __align__(256) float g_invin [N_NODES];
__device__ __align__(256) float g_invout[N_NODES];
__device__ __align__(256) float g_degout[N_NODES];
__device__ __align__(256) float g_degin [N_NODES];
__device__ __align__(256) float g_gsum [N_GRAPHS * 10];

// ---------------- vector reductions (sm_90+) --------------------------------
__device__ __forceinline__ void red_add_v4(float* addr, float4 v) {
    asm volatile("red.global.add.v4.f32 [%0], {%1,%2,%3,%4};"
                 :: "l"(addr), "f"(v.x), "f"(v.y), "f"(v.z), "f"(v.w) : "memory");
}
__device__ __forceinline__ void red_add_v2(float* addr, float2 v) {
    asm volatile("red.global.add.v2.f32 [%0], {%1,%2};"
                 :: "l"(addr), "f"(v.x), "f"(v.y) : "memory");
}

// ---------------- kernels ----------------------------------------------------

// Zero all accumulators
__global__ void k_zero() {
    int i = blockIdx.x * blockDim.x + threadIdx.x;
    if (i < N_NODES * 8)   g_agg1[i] = 0.f;
    if (i < N_NODES * 16)  g_agg2[i] = 0.f;
    if (i < N_NODES * 12)  g_agg3[i] = 0.f;
    if (i < N_NODES)     { g_degout[i] = 0.f; g_degin[i] = 0.f; }
    if (i < N_GRAPHS * 10) g_gsum[i] = 0.f;
}

// Degree count: 4 edges per thread, vectorized index loads, batched REDs
__global__ void k_degree(const int* __restrict__ src, const int* __restrict__ dst) {
    int t = blockIdx.x * blockDim.x + threadIdx.x;
    int base = t * 4;
    if (base >= N_EDGES) return;
    int4 s = *(const int4*)(src + base);
    int4 d = *(const int4*)(dst + base);
    atomicAdd(&g_degout[s.x], 1.f);
    atomicAdd(&g_degout[s.y], 1.f);
    atomicAdd(&g_degout[s.z], 1.f);
    atomicAdd(&g_degout[s.w], 1.f);
    atomicAdd(&g_degin [d.x], 1.f);
    atomicAdd(&g_degin [d.y], 1.f);
    atomicAdd(&g_degin [d.z], 1.f);
    atomicAdd(&g_degin [d.w], 1.f);
}

// inv-sqrt degrees + pre-scale node features by inv_sqrt_out
__global__ void k_prep(const float* __restrict__ n_feat) {
    int i = blockIdx.x * blockDim.x + threadIdx.x;
    if (i >= N_NODES) return;
    float io = rsqrtf(fmaxf(g_degout[i], 1.f));
    float ii = rsqrtf(fmaxf(g_degin [i], 1.f));
    g_invout[i] = io;
    g_invin [i] = ii;
    const float4* xr = (const float4*)(n_feat + (size_t)i * 8);
    float4 a = xr[0], b = xr[1];
    a.x *= io; a.y *= io; a.z *= io; a.w *= io;
    b.x *= io; b.y *= io; b.z *= io; b.w *= io;
    float4* o = (float4*)(g_x1 + (size_t)i * 8);
    o[0] = a; o[1] = b;
}

// Layer 1 edge scatter: agg1[dst] += x1[src]  (8 floats), 4 edges/thread
__global__ void k_scatter1(const int* __restrict__ src, const int* __restrict__ dst) {
    int t = blockIdx.x * blockDim.x + threadIdx.x;
    int base = t * 4;
    if (base >= N_EDGES) return;
    int4 s = *(const int4*)(src + base);
    int4 d = *(const int4*)(dst + base);
    // issue all gathers first (8 LDG.128 in flight)
    const float4* r0 = (const float4*)(g_x1 + (size_t)s.x * 8);
    const float4* r1 = (const float4*)(g_x1 + (size_t)s.y * 8);
    const float4* r2 = (const float4*)(g_x1 + (size_t)s.z * 8);
    const float4* r3 = (const float4*)(g_x1 + (size_t)s.w * 8);
    float4 a0 = r0[0], b0 = r0[1];
    float4 a1 = r1[0], b1 = r1[1];
    float4 a2 = r2[0], b2 = r2[1];
    float4 a3 = r3[0], b3 = r3[1];
    float* o0 = g_agg1 + (size_t)d.x * 8;
    float* o1 = g_agg1 + (size_t)d.y * 8;
    float* o2 = g_agg1 + (size_t)d.z * 8;
    float* o3 = g_agg1 + (size_t)d.w * 8;
    red_add_v4(o0, a0); red_add_v4(o0 + 4, b0);
    red_add_v4(o1, a1); red_add_v4(o1 + 4, b1);
    red_add_v4(o2, a2); red_add_v4(o2 + 4, b2);
    red_add_v4(o3, a3); red_add_v4(o3 + 4, b3);
}

// Layer 1 dense: h1s = relu(agg1*invin @ W1 + b1) * invout    (8 -> 16)
__global__ void k_dense1(const float* __restrict__ W1, const float* __restrict__ b1) {
    __shared__ float sW[8 * 16];
    __shared__ float sb[16];
    int t = threadIdx.x;
    if (t < 128) sW[t] = W1[t];
    if (t < 16)  sb[t] = b1[t];
    __syncthreads();
    int i = blockIdx.x * blockDim.x + t;
    if (i >= N_NODES) return;
    float ii = g_invin[i], io = g_invout[i];
    const float4* ar = (const float4*)(g_agg1 + (size_t)i * 8);
    float4 p = ar[0], q = ar[1];
    float a[8] = {p.x*ii, p.y*ii, p.z*ii, p.w*ii, q.x*ii, q.y*ii, q.z*ii, q.w*ii};
    float acc[16];
    #pragma unroll
    for (int j = 0; j < 16; j++) acc[j] = sb[j];
    #pragma unroll
    for (int k = 0; k < 8; k++)
        #pragma unroll
        for (int j = 0; j < 16; j++)
            acc[j] = fmaf(a[k], sW[k * 16 + j], acc[j]);
    float4* o = (float4*)(g_h1s + (size_t)i * 16);
    #pragma unroll
    for (int v = 0; v < 4; v++) {
        float4 r;
        r.x = fmaxf(acc[v*4+0], 0.f) * io;
        r.y = fmaxf(acc[v*4+1], 0.f) * io;
        r.z = fmaxf(acc[v*4+2], 0.f) * io;
        r.w = fmaxf(acc[v*4+3], 0.f) * io;
        o[v] = r;
    }
}

// Layer 2 edge scatter: agg2[dst] += h1s[src]  (16 floats), 2 edges/thread
__global__ void k_scatter2(const int* __restrict__ src, const int* __restrict__ dst) {
    int t = blockIdx.x * blockDim.x + threadIdx.x;
    int base = t * 2;
    if (base >= N_EDGES) return;
    int2 s = *(const int2*)(src + base);
    int2 d = *(const int2*)(dst + base);
    const float4* r0 = (const float4*)(g_h1s + (size_t)s.x * 16);
    const float4* r1 = (const float4*)(g_h1s + (size_t)s.y * 16);
    float4 a0 = r0[0], b0 = r0[1], c0 = r0[2], w0 = r0[3];
    float4 a1 = r1[0], b1 = r1[1], c1 = r1[2], w1 = r1[3];
    float* o0 = g_agg2 + (size_t)d.x * 16;
    float* o1 = g_agg2 + (size_t)d.y * 16;
    red_add_v4(o0,      a0); red_add_v4(o0 + 4,  b0);
    red_add_v4(o0 + 8,  c0); red_add_v4(o0 + 12, w0);
    red_add_v4(o1,      a1); red_add_v4(o1 + 4,  b1);
    red_add_v4(o1 + 8,  c1); red_add_v4(o1 + 12, w1);
}

// Layer 2 dense + layer 3 pre-matmul fused:
//   h2 = relu(agg2*invin @ W2 + b2)  (never materialized)
//   z3 = (h2 * invout) @ W3          (10 floats, stride 12)
__global__ void k_dense2(const float* __restrict__ W2, const float* __restrict__ b2,
                         const float* __restrict__ W3) {
    __shared__ float sW2[16 * 32];
    __shared__ float sb2[32];
    __shared__ float sW3[32 * 10];
    int t = threadIdx.x;
    for (int j = t; j < 16 * 32; j += blockDim.x) sW2[j] = W2[j];
    for (int j = t; j < 32 * 10; j += blockDim.x) sW3[j] = W3[j];
    if (t < 32) sb2[t] = b2[t];
    __syncthreads();
    int i = blockIdx.x * blockDim.x + t;
    if (i >= N_NODES) return;
    float ii = g_invin[i], io = g_invout[i];
    float a[16];
    const float4* ar = (const float4*)(g_agg2 + (size_t)i * 16);
    #pragma unroll
    for (int v = 0; v < 4; v++) {
        float4 p = ar[v];
        a[v*4+0] = p.x*ii; a[v*4+1] = p.y*ii; a[v*4+2] = p.z*ii; a[v*4+3] = p.w*ii;
    }
    float acc[32];
    #pragma unroll
    for (int j = 0; j < 32; j++) acc[j] = sb2[j];
    #pragma unroll
    for (int k = 0; k < 16; k++)
        #pragma unroll
        for (int j = 0; j < 32; j++)
            acc[j] = fmaf(a[k], sW2[k * 32 + j], acc[j]);
    float z[10];
    #pragma unroll
    for (int j = 0; j < 10; j++) z[j] = 0.f;
    #pragma unroll
    for (int k = 0; k < 32; k++) {
        float h = fmaxf(acc[k], 0.f) * io;
        #pragma unroll
        for (int j = 0; j < 10; j++)
            z[j] = fmaf(h, sW3[k * 10 + j], z[j]);
    }
    float* o = g_z3 + (size_t)i * 12;
    *(float4*)(o)     = make_float4(z[0], z[1], z[2], z[3]);
    *(float4*)(o + 4) = make_float4(z[4], z[5], z[6], z[7]);
    *(float2*)(o + 8) = make_float2(z[8], z[9]);
}

// Layer 3 edge scatter: agg3[dst] += z3[src]  (10 floats, stride 12), 2 edges/thread
__global__ void k_scatter3(const int* __restrict__ src, const int* __restrict__ dst) {
    int t = blockIdx.x * blockDim.x + threadIdx.x;
    int base = t * 2;
    if (base >= N_EDGES) return;
    int2 s = *(const int2*)(src + base);
    int2 d = *(const int2*)(dst + base);
    const float* r0 = g_z3 + (size_t)s.x * 12;
    const float* r1 = g_z3 + (size_t)s.y * 12;
    float4 a0 = *(const float4*)(r0);
    float4 b0 = *(const float4*)(r0 + 4);
    float2 c0 = *(const float2*)(r0 + 8);
    float4 a1 = *(const float4*)(r1);
    float4 b1 = *(const float4*)(r1 + 4);
    float2 c1 = *(const float2*)(r1 + 8);
    float* o0 = g_agg3 + (size_t)d.x * 12;
    float* o1 = g_agg3 + (size_t)d.y * 12;
    red_add_v4(o0, a0); red_add_v4(o0 + 4, b0); red_add_v2(o0 + 8, c0);
    red_add_v4(o1, a1); red_add_v4(o1 + 4, b1); red_add_v2(o1 + 8, c1);
}

// Per-graph sum pooling (graph_ids sorted -> shared-mem accumulate, skip-zero flush)
__global__ void k_pool(const int* __restrict__ gids) {
    __shared__ float ssum[N_GRAPHS * 10];
    int t = threadIdx.x;
    for (int j = t; j < N_GRAPHS * 10; j += blockDim.x) ssum[j] = 0.f;
    __syncthreads();
    int i = blockIdx.x * blockDim.x + t;
    if (i < N_NODES) {
        int g = gids[i];
        float ii = g_invin[i];
        const float* r = g_agg3 + (size_t)i * 12;
        #pragma unroll
        for (int j = 0; j < 10; j++)
            atomicAdd(&ssum[g * 10 + j], r[j] * ii);
    }
    __syncthreads();
    for (int j = t; j < N_GRAPHS * 10; j += blockDim.x) {
        float v = ssum[j];
        if (v != 0.f) atomicAdd(&g_gsum[j], v);
    }
}

__device__ __forceinline__ int lowerb(const int* __restrict__ a, int n, int v) {
    int lo = 0, hi = n;
    while (lo < hi) {
        int m = (lo + hi) >> 1;
        if (a[m] < v) lo = m + 1; else hi = m;
    }
    return lo;
}

// Finalize: out[g][j] = gsum[g][j] / max(count_g,1) + b3[j]
__global__ void k_final(const int* __restrict__ gids, const float* __restrict__ b3,
                        float* __restrict__ out) {
    int i = blockIdx.x * blockDim.x + threadIdx.x;
    if (i >= N_GRAPHS * 10) return;
    int g = i / 10, j = i % 10;
    int lo = lowerb(gids, N_NODES, g);
    int hi = lowerb(gids, N_NODES, g + 1);
    float cnt = (float)(hi - lo);
    out[i] = g_gsum[i] / fmaxf(cnt, 1.f) + b3[j];
}

// ---------------- launch ------------------------------------------------------
extern "C" void kernel_launch(void* const* d_in, const int* in_sizes, int n_in,
                              void* d_out, int out_size) {
    const float* n_feat = (const float*)d_in[0];
    const int*   src    = (const int*)  d_in[1];
    const int*   dst    = (const int*)  d_in[2];
    const int*   gids   = (const int*)  d_in[3];
    const float* W1     = (const float*)d_in[4];
    const float* b1     = (const float*)d_in[5];
    const float* W2     = (const float*)d_in[6];
    const float* b2     = (const float*)d_in[7];
    const float* W3     = (const float*)d_in[8];
    const float* b3     = (const float*)d_in[9];
    float* out = (float*)d_out;

    const int TB = 256;
    const int nb  = (N_NODES + TB - 1) / TB;              // node blocks
    const int zb  = (N_NODES * 16 + TB - 1) / TB;         // zero blocks
    const int eb4 = (N_EDGES / 4 + TB - 1) / TB;          // 4 edges/thread
    const int eb2 = (N_EDGES / 2 + TB - 1) / TB;          // 2 edges/thread

    k_zero    <<<zb, TB>>>();
    k_degree  <<<eb4, TB>>>(src, dst);
    k_prep    <<<nb, TB>>>(n_feat);
    k_scatter1<<<eb4, TB>>>(src, dst);
    k_dense1  <<<nb, TB>>>(W1, b1);
    k_scatter2<<<eb2, TB>>>(src, dst);
    k_dense2  <<<nb, TB>>>(W2, b2, W3);
    k_scatter3<<<eb2, TB>>>(src, dst);
    k_pool    <<<nb, TB>>>(gids);
    k_final   <<<(N_GRAPHS * 10 + TB - 1) / TB, TB>>>(gids, b3, out);
}

// round 3
// speedup vs baseline: 1.2937x; 1.2937x over previous
#include <cuda_runtime.h>
#include <cuda_bf16.h>

#define N_NODES  100000
#define N_EDGES  1600000
#define N_GRAPHS 64
#define NB_SCAN  98          // 98 * 1024 >= N_NODES

// ---------------- scratch (device globals) ----------------------------------
__device__ __align__(256) float g_x1   [N_NODES * 8];   // n_feat * inv_sqrt_out
__device__ __align__(256) float g_h1s  [N_NODES * 16];  // relu(h1) * inv_sqrt_out
__device__ __align__(256) float g_z3   [N_NODES * 12];  // (h2*invout)@W3 (10 used)
__device__ __align__(256) float g_invin [N_NODES];
__device__ __align__(256) int   g_degout[N_NODES];
__device__ __align__(256) int   g_degin [N_NODES];
__device__ __align__(256) int   g_rowptr[N_NODES + 1];
__device__ __align__(256) int   g_fillpos[N_NODES];
__device__ __align__(256) int   g_csr_src[N_EDGES];
__device__ __align__(256) int   g_partials[NB_SCAN];
__device__ __align__(256) float g_gsum [N_GRAPHS * 10];

__device__ __forceinline__ float4 f4add(float4 a, float4 b) {
    return make_float4(a.x + b.x, a.y + b.y, a.z + b.z, a.w + b.w);
}

// ---------------- CSR build ---------------------------------------------------

__global__ void k_degree(const int* __restrict__ src, const int* __restrict__ dst) {
    int t = blockIdx.x * blockDim.x + threadIdx.x;
    int base = t * 4;
    if (base >= N_EDGES) return;
    int4 s = *(const int4*)(src + base);
    int4 d = *(const int4*)(dst + base);
    atomicAdd(&g_degout[s.x], 1); atomicAdd(&g_degout[s.y], 1);
    atomicAdd(&g_degout[s.z], 1); atomicAdd(&g_degout[s.w], 1);
    atomicAdd(&g_degin [d.x], 1); atomicAdd(&g_degin [d.y], 1);
    atomicAdd(&g_degin [d.z], 1); atomicAdd(&g_degin [d.w], 1);
}

// zero the degree counters and gsum before k_degree
__global__ void k_zero() {
    int i = blockIdx.x * blockDim.x + threadIdx.x;
    if (i < N_NODES) { g_degout[i] = 0; g_degin[i] = 0; }
    if (i < N_GRAPHS * 10) g_gsum[i] = 0.f;
}

// block-wise exclusive scan of degin; store per-block totals
__global__ void k_scanA() {
    __shared__ int sh[1024];
    int t = threadIdx.x;
    int i = blockIdx.x * 1024 + t;
    int val = (i < N_NODES) ? g_degin[i] : 0;
    sh[t] = val;
    __syncthreads();
    #pragma unroll
    for (int off = 1; off < 1024; off <<= 1) {
        int x = (t >= off) ? sh[t - off] : 0;
        __syncthreads();
        sh[t] += x;
        __syncthreads();
    }
    if (i < N_NODES) g_rowptr[i] = sh[t] - val;   // exclusive, pre block-offset
    if (t == 1023) g_partials[blockIdx.x] = sh[t];
}

// scan the 98 block totals (single block; serial in shared — tiny)
__global__ void k_scanB() {
    __shared__ int sh[NB_SCAN];
    int t = threadIdx.x;
    if (t < NB_SCAN) sh[t] = g_partials[t];
    __syncthreads();
    if (t == 0) {
        int run = 0;
        for (int b = 0; b < NB_SCAN; b++) { int v = sh[b]; sh[b] = run; run += v; }
    }
    __syncthreads();
    if (t < NB_SCAN) g_partials[t] = sh[t];
}

// add block offsets, init fill positions
__global__ void k_scanC() {
    int t = threadIdx.x;
    int i = blockIdx.x * 1024 + t;
    if (i < N_NODES) {
        int r = g_rowptr[i] + g_partials[blockIdx.x];
        g_rowptr[i] = r;
        g_fillpos[i] = r;
    }
    if (i == 0) g_rowptr[N_NODES] = N_EDGES;
}

// scatter edge src ids into dst-sorted CSR buckets
__global__ void k_fill(const int* __restrict__ src, const int* __restrict__ dst) {
    int t = blockIdx.x * blockDim.x + threadIdx.x;
    int base = t * 2;
    if (base >= N_EDGES) return;
    int2 s = *(const int2*)(src + base);
    int2 d = *(const int2*)(dst + base);
    int p0 = atomicAdd(&g_fillpos[d.x], 1);
    int p1 = atomicAdd(&g_fillpos[d.y], 1);
    g_csr_src[p0] = s.x;
    g_csr_src[p1] = s.y;
}

// inv-sqrt degrees + pre-scale node features by inv_sqrt_out
__global__ void k_prep(const float* __restrict__ n_feat) {
    int i = blockIdx.x * blockDim.x + threadIdx.x;
    if (i >= N_NODES) return;
    float io = rsqrtf(fmaxf((float)g_degout[i], 1.f));
    float ii = rsqrtf(fmaxf((float)g_degin [i], 1.f));
    g_invin[i] = ii;
    const float4* xr = (const float4*)(n_feat + (size_t)i * 8);
    float4 a = xr[0], b = xr[1];
    a.x *= io; a.y *= io; a.z *= io; a.w *= io;
    b.x *= io; b.y *= io; b.z *= io; b.w *= io;
    float4* o = (float4*)(g_x1 + (size_t)i * 8);
    o[0] = a; o[1] = b;
    // stash invout in g_z3 row slot 10..11? no — keep a dedicated read below:
}

__device__ __align__(256) float g_invout[N_NODES];
__global__ void k_prep_io() {
    int i = blockIdx.x * blockDim.x + threadIdx.x;
    if (i >= N_NODES) return;
    g_invout[i] = rsqrtf(fmaxf((float)g_degout[i], 1.f));
}

// ---------------- fused gather + dense layers --------------------------------

// Layer 1: acc = sum_{e in in(i)} x1[src[e]]; h1s = relu(acc*ii @ W1 + b1) * io
__global__ void k_layer1(const float* __restrict__ W1, const float* __restrict__ b1) {
    __shared__ float sW[8 * 16];
    __shared__ float sb[16];
    int t = threadIdx.x;
    if (t < 128) sW[t] = W1[t];
    if (t < 16)  sb[t] = b1[t];
    __syncthreads();
    int i = blockIdx.x * blockDim.x + t;
    if (i >= N_NODES) return;
    int beg = g_rowptr[i], end = g_rowptr[i + 1];
    float4 A = make_float4(0, 0, 0, 0), B = make_float4(0, 0, 0, 0);
    int e = beg;
    for (; e + 4 <= end; e += 4) {
        int s0 = g_csr_src[e], s1 = g_csr_src[e + 1];
        int s2 = g_csr_src[e + 2], s3 = g_csr_src[e + 3];
        const float4* p0 = (const float4*)(g_x1 + (size_t)s0 * 8);
        const float4* p1 = (const float4*)(g_x1 + (size_t)s1 * 8);
        const float4* p2 = (const float4*)(g_x1 + (size_t)s2 * 8);
        const float4* p3 = (const float4*)(g_x1 + (size_t)s3 * 8);
        float4 a0 = p0[0], b0 = p0[1];
        float4 a1 = p1[0], b1v = p1[1];
        float4 a2 = p2[0], b2 = p2[1];
        float4 a3 = p3[0], b3 = p3[1];
        A = f4add(A, f4add(f4add(a0, a1), f4add(a2, a3)));
        B = f4add(B, f4add(f4add(b0, b1v), f4add(b2, b3)));
    }
    for (; e < end; e++) {
        int s = g_csr_src[e];
        const float4* p = (const float4*)(g_x1 + (size_t)s * 8);
        A = f4add(A, p[0]);
        B = f4add(B, p[1]);
    }
    float ii = g_invin[i], io = g_invout[i];
    float a[8] = {A.x*ii, A.y*ii, A.z*ii, A.w*ii, B.x*ii, B.y*ii, B.z*ii, B.w*ii};
    float acc[16];
    #pragma unroll
    for (int j = 0; j < 16; j++) acc[j] = sb[j];
    #pragma unroll
    for (int k = 0; k < 8; k++)
        #pragma unroll
        for (int j = 0; j < 16; j++)
            acc[j] = fmaf(a[k], sW[k * 16 + j], acc[j]);
    float4* o = (float4*)(g_h1s + (size_t)i * 16);
    #pragma unroll
    for (int v = 0; v < 4; v++)
        o[v] = make_float4(fmaxf(acc[v*4+0], 0.f) * io, fmaxf(acc[v*4+1], 0.f) * io,
                           fmaxf(acc[v*4+2], 0.f) * io, fmaxf(acc[v*4+3], 0.f) * io);
}

// Layer 2+3a: acc16 = sum h1s[src]; h2 = relu(acc*ii @ W2 + b2);
//             z3 = (h2 * io) @ W3   (10 floats, stride 12)
__global__ void k_layer2(const float* __restrict__ W2, const float* __restrict__ b2,
                         const float* __restrict__ W3) {
    __shared__ float sW2[16 * 32];
    __shared__ float sb2[32];
    __shared__ float sW3[32 * 10];
    int t = threadIdx.x;
    for (int j = t; j < 16 * 32; j += blockDim.x) sW2[j] = W2[j];
    for (int j = t; j < 32 * 10; j += blockDim.x) sW3[j] = W3[j];
    if (t < 32) sb2[t] = b2[t];
    __syncthreads();
    int i = blockIdx.x * blockDim.x + t;
    if (i >= N_NODES) return;
    int beg = g_rowptr[i], end = g_rowptr[i + 1];
    float4 A = make_float4(0,0,0,0), B = make_float4(0,0,0,0);
    float4 C = make_float4(0,0,0,0), D = make_float4(0,0,0,0);
    int e = beg;
    for (; e + 2 <= end; e += 2) {
        int s0 = g_csr_src[e], s1 = g_csr_src[e + 1];
        const float4* p0 = (const float4*)(g_h1s + (size_t)s0 * 16);
        const float4* p1 = (const float4*)(g_h1s + (size_t)s1 * 16);
        float4 a0 = p0[0], b0 = p0[1], c0 = p0[2], d0 = p0[3];
        float4 a1 = p1[0], b1 = p1[1], c1 = p1[2], d1 = p1[3];
        A = f4add(A, f4add(a0, a1));
        B = f4add(B, f4add(b0, b1));
        C = f4add(C, f4add(c0, c1));
        D = f4add(D, f4add(d0, d1));
    }
    for (; e < end; e++) {
        int s = g_csr_src[e];
        const float4* p = (const float4*)(g_h1s + (size_t)s * 16);
        A = f4add(A, p[0]); B = f4add(B, p[1]);
        C = f4add(C, p[2]); D = f4add(D, p[3]);
    }
    float ii = g_invin[i], io = g_invout[i];
    float a[16] = {A.x*ii, A.y*ii, A.z*ii, A.w*ii, B.x*ii, B.y*ii, B.z*ii, B.w*ii,
                   C.x*ii, C.y*ii, C.z*ii, C.w*ii, D.x*ii, D.y*ii, D.z*ii, D.w*ii};
    float acc[32];
    #pragma unroll
    for (int j = 0; j < 32; j++) acc[j] = sb2[j];
    #pragma unroll
    for (int k = 0; k < 16; k++)
        #pragma unroll
        for (int j = 0; j < 32; j++)
            acc[j] = fmaf(a[k], sW2[k * 32 + j], acc[j]);
    float z[10];
    #pragma unroll
    for (int j = 0; j < 10; j++) z[j] = 0.f;
    #pragma unroll
    for (int k = 0; k < 32; k++) {
        float h = fmaxf(acc[k], 0.f) * io;
        #pragma unroll
        for (int j = 0; j < 10; j++)
            z[j] = fmaf(h, sW3[k * 10 + j], z[j]);
    }
    float* o = g_z3 + (size_t)i * 12;
    *(float4*)(o)     = make_float4(z[0], z[1], z[2], z[3]);
    *(float4*)(o + 4) = make_float4(z[4], z[5], z[6], z[7]);
    *(float2*)(o + 8) = make_float2(z[8], z[9]);
}

// Layer 3b + pool: node out = (sum z3[src]) * ii; per-graph sum via shared mem
__global__ void k_layer3(const int* __restrict__ gids) {
    __shared__ float ssum[N_GRAPHS * 10];
    int t = threadIdx.x;
    for (int j = t; j < N_GRAPHS * 10; j += blockDim.x) ssum[j] = 0.f;
    __syncthreads();
    int i = blockIdx.x * blockDim.x + t;
    float v[10];
    int g = -1;
    if (i < N_NODES) {
        int beg = g_rowptr[i], end = g_rowptr[i + 1];
        float4 A = make_float4(0,0,0,0), B = make_float4(0,0,0,0);
        float2 C = make_float2(0,0);
        int e = beg;
        for (; e + 2 <= end; e += 2) {
            int s0 = g_csr_src[e], s1 = g_csr_src[e + 1];
            const float* r0 = g_z3 + (size_t)s0 * 12;
            const float* r1 = g_z3 + (size_t)s1 * 12;
            float4 a0 = *(const float4*)(r0);
            float4 b0 = *(const float4*)(r0 + 4);
            float2 c0 = *(const float2*)(r0 + 8);
            float4 a1 = *(const float4*)(r1);
            float4 b1 = *(const float4*)(r1 + 4);
            float2 c1 = *(const float2*)(r1 + 8);
            A = f4add(A, f4add(a0, a1));
            B = f4add(B, f4add(b0, b1));
            C.x += c0.x + c1.x; C.y += c0.y + c1.y;
        }
        for (; e < end; e++) {
            int s = g_csr_src[e];
            const float* r = g_z3 + (size_t)s * 12;
            float4 a = *(const float4*)(r);
            float4 b = *(const float4*)(r + 4);
            float2 c = *(const float2*)(r + 8);
            A = f4add(A, a); B = f4add(B, b);
            C.x += c.x; C.y += c.y;
        }
        float ii = g_invin[i];
        v[0]=A.x*ii; v[1]=A.y*ii; v[2]=A.z*ii; v[3]=A.w*ii;
        v[4]=B.x*ii; v[5]=B.y*ii; v[6]=B.z*ii; v[7]=B.w*ii;
        v[8]=C.x*ii; v[9]=C.y*ii;
        g = gids[i];
    } else {
        #pragma unroll
        for (int j = 0; j < 10; j++) v[j] = 0.f;
    }
    // warp-uniform graph id fast path (graph_ids are sorted)
    int leader = __shfl_sync(0xffffffffu, g, 0);
    bool uni = __all_sync(0xffffffffu, g == leader);
    if (uni && leader >= 0) {
        #pragma unroll
        for (int j = 0; j < 10; j++) {
            float s = v[j];
            #pragma unroll
            for (int off = 16; off > 0; off >>= 1)
                s += __shfl_xor_sync(0xffffffffu, s, off);
            if ((t & 31) == 0) atomicAdd(&ssum[leader * 10 + j], s);
        }
    } else if (g >= 0) {
        #pragma unroll
        for (int j = 0; j < 10; j++)
            atomicAdd(&ssum[g * 10 + j], v[j]);
    }
    __syncthreads();
    for (int j = t; j < N_GRAPHS * 10; j += blockDim.x) {
        float s = ssum[j];
        if (s != 0.f) atomicAdd(&g_gsum[j], s);
    }
}

__device__ __forceinline__ int lowerb(const int* __restrict__ a, int n, int v) {
    int lo = 0, hi = n;
    while (lo < hi) {
        int m = (lo + hi) >> 1;
        if (a[m] < v) lo = m + 1; else hi = m;
    }
    return lo;
}

__global__ void k_final(const int* __restrict__ gids, const float* __restrict__ b3,
                        float* __restrict__ out) {
    int i = blockIdx.x * blockDim.x + threadIdx.x;
    if (i >= N_GRAPHS * 10) return;
    int g = i / 10, j = i % 10;
    int lo = lowerb(gids, N_NODES, g);
    int hi = lowerb(gids, N_NODES, g + 1);
    float cnt = (float)(hi - lo);
    out[i] = g_gsum[i] / fmaxf(cnt, 1.f) + b3[j];
}

// ---------------- launch ------------------------------------------------------
extern "C" void kernel_launch(void* const* d_in, const int* in_sizes, int n_in,
                              void* d_out, int out_size) {
    const float* n_feat = (const float*)d_in[0];
    const int*   src    = (const int*)  d_in[1];
    const int*   dst    = (const int*)  d_in[2];
    const int*   gids   = (const int*)  d_in[3];
    const float* W1     = (const float*)d_in[4];
    const float* b1     = (const float*)d_in[5];
    const float* W2     = (const float*)d_in[6];
    const float* b2     = (const float*)d_in[7];
    const float* W3     = (const float*)d_in[8];
    const float* b3     = (const float*)d_in[9];
    float* out = (float*)d_out;

    const int TB = 256;
    const int nb  = (N_NODES + TB - 1) / TB;
    const int eb4 = (N_EDGES / 4 + TB - 1) / TB;
    const int eb2 = (N_EDGES / 2 + TB - 1) / TB;

    k_zero   <<<nb, TB>>>();
    k_degree <<<eb4, TB>>>(src, dst);
    k_scanA  <<<NB_SCAN, 1024>>>();
    k_scanB  <<<1, 128>>>();
    k_scanC  <<<NB_SCAN, 1024>>>();
    k_fill   <<<eb2, TB>>>(src, dst);
    k_prep_io<<<nb, TB>>>();
    k_prep   <<<nb, TB>>>(n_feat);
    k_layer1 <<<nb, TB>>>(W1, b1);
    k_layer2 <<<nb, TB>>>(W2, b2, W3);
    k_layer3 <<<NB_SCAN, 1024>>>(gids);
    k_final  <<<3, TB>>>(gids, b3, out);
}

// round 4
// speedup vs baseline: 1.5538x; 1.2010x over previous
#include <cuda_runtime.h>
#include <cuda_fp16.h>

#define N_NODES  100000
#define N_EDGES  1600000
#define N_GRAPHS 64

// ---------------- scratch (device globals) ----------------------------------
__device__ __align__(256) float   g_x1   [N_NODES * 8];   // n_feat * inv_sqrt_out (fp32)
__device__ __align__(256) __half2 g_h1s  [N_NODES * 8];   // relu(h1)*invout, fp16, 16 vals
__device__ __align__(256) __half2 g_z3h  [N_NODES * 8];   // (h2*invout)@W3, fp16, 10 vals (stride 8 half2)
__device__ __align__(256) float   g_invin [N_NODES];
__device__ __align__(256) float   g_invout[N_NODES];
__device__ __align__(256) int     g_degout[N_NODES];
__device__ __align__(256) int     g_degin [N_NODES];
__device__ __align__(256) int     g_rowptr[N_NODES];      // bucket start (arbitrary order)
__device__ __align__(256) int     g_fillpos[N_NODES];
__device__ __align__(256) int     g_csr_src[N_EDGES];
__device__                int     g_cursor;
__device__ __align__(256) float   g_gsum [N_GRAPHS * 10];

__device__ __forceinline__ float4 f4add(float4 a, float4 b) {
    return make_float4(a.x + b.x, a.y + b.y, a.z + b.z, a.w + b.w);
}
__device__ __forceinline__ void acc_h2(float& a0, float& a1, unsigned bits) {
    __half2 h = *reinterpret_cast<__half2*>(&bits);
    float2 f = __half22float2(h);
    a0 += f.x; a1 += f.y;
}

// ---------------- CSR build ---------------------------------------------------

__global__ void k_zero() {
    int i = blockIdx.x * blockDim.x + threadIdx.x;
    if (i < N_NODES) { g_degout[i] = 0; g_degin[i] = 0; }
    if (i < N_GRAPHS * 10) g_gsum[i] = 0.f;
    if (i == 0) g_cursor = 0;
}

__global__ void k_degree(const int* __restrict__ src, const int* __restrict__ dst) {
    int t = blockIdx.x * blockDim.x + threadIdx.x;
    int base = t * 4;
    if (base >= N_EDGES) return;
    int4 s = *(const int4*)(src + base);
    int4 d = *(const int4*)(dst + base);
    atomicAdd(&g_degout[s.x], 1); atomicAdd(&g_degout[s.y], 1);
    atomicAdd(&g_degout[s.z], 1); atomicAdd(&g_degout[s.w], 1);
    atomicAdd(&g_degin [d.x], 1); atomicAdd(&g_degin [d.y], 1);
    atomicAdd(&g_degin [d.z], 1); atomicAdd(&g_degin [d.w], 1);
}

// inv-sqrt degrees, pre-scale features, and warp-aggregated CSR bucket alloc
__global__ void k_prep(const float* __restrict__ n_feat) {
    int i = blockIdx.x * blockDim.x + threadIdx.x;
    int lane = threadIdx.x & 31;
    bool ok = (i < N_NODES);
    int deg = ok ? g_degin[i] : 0;
    // warp inclusive scan of deg
    int scan = deg;
    #pragma unroll
    for (int off = 1; off < 32; off <<= 1) {
        int n = __shfl_up_sync(0xffffffffu, scan, off);
        if (lane >= off) scan += n;
    }
    int total = __shfl_sync(0xffffffffu, scan, 31);
    int base = 0;
    if (lane == 31) base = atomicAdd(&g_cursor, total);
    base = __shfl_sync(0xffffffffu, base, 31);
    if (!ok) return;
    int start = base + scan - deg;
    g_rowptr[i]  = start;
    g_fillpos[i] = start;

    float io = rsqrtf(fmaxf((float)g_degout[i], 1.f));
    float ii = rsqrtf(fmaxf((float)deg, 1.f));
    g_invin[i]  = ii;
    g_invout[i] = io;
    const float4* xr = (const float4*)(n_feat + (size_t)i * 8);
    float4 a = xr[0], b = xr[1];
    a.x *= io; a.y *= io; a.z *= io; a.w *= io;
    b.x *= io; b.y *= io; b.z *= io; b.w *= io;
    float4* o = (float4*)(g_x1 + (size_t)i * 8);
    o[0] = a; o[1] = b;
}

// scatter edge src ids into dst buckets
__global__ void k_fill(const int* __restrict__ src, const int* __restrict__ dst) {
    int t = blockIdx.x * blockDim.x + threadIdx.x;
    int base = t * 2;
    if (base >= N_EDGES) return;
    int2 s = *(const int2*)(src + base);
    int2 d = *(const int2*)(dst + base);
    int p0 = atomicAdd(&g_fillpos[d.x], 1);
    int p1 = atomicAdd(&g_fillpos[d.y], 1);
    g_csr_src[p0] = s.x;
    g_csr_src[p1] = s.y;
}

// ---------------- fused gather + dense layers --------------------------------

// Layer 1: acc8 = sum x1[src] (fp32); h1s = relu(acc*ii @ W1 + b1) * io -> fp16
__global__ void k_layer1(const float* __restrict__ W1, const float* __restrict__ b1) {
    __shared__ float sW[8 * 16];
    __shared__ float sb[16];
    int t = threadIdx.x;
    if (t < 128) sW[t] = W1[t];
    if (t < 16)  sb[t] = b1[t];
    __syncthreads();
    int i = blockIdx.x * blockDim.x + t;
    if (i >= N_NODES) return;
    int beg = g_rowptr[i];
    int end = beg + g_degin[i];
    float4 A = make_float4(0, 0, 0, 0), B = make_float4(0, 0, 0, 0);
    int e = beg;
    for (; e + 4 <= end; e += 4) {
        int s0 = g_csr_src[e], s1 = g_csr_src[e + 1];
        int s2 = g_csr_src[e + 2], s3 = g_csr_src[e + 3];
        const float4* p0 = (const float4*)(g_x1 + (size_t)s0 * 8);
        const float4* p1 = (const float4*)(g_x1 + (size_t)s1 * 8);
        const float4* p2 = (const float4*)(g_x1 + (size_t)s2 * 8);
        const float4* p3 = (const float4*)(g_x1 + (size_t)s3 * 8);
        float4 a0 = p0[0], b0 = p0[1];
        float4 a1 = p1[0], b1v = p1[1];
        float4 a2 = p2[0], b2 = p2[1];
        float4 a3 = p3[0], b3 = p3[1];
        A = f4add(A, f4add(f4add(a0, a1), f4add(a2, a3)));
        B = f4add(B, f4add(f4add(b0, b1v), f4add(b2, b3)));
    }
    for (; e < end; e++) {
        int s = g_csr_src[e];
        const float4* p = (const float4*)(g_x1 + (size_t)s * 8);
        A = f4add(A, p[0]);
        B = f4add(B, p[1]);
    }
    float ii = g_invin[i], io = g_invout[i];
    float a[8] = {A.x*ii, A.y*ii, A.z*ii, A.w*ii, B.x*ii, B.y*ii, B.z*ii, B.w*ii};
    float acc[16];
    #pragma unroll
    for (int j = 0; j < 16; j++) acc[j] = sb[j];
    #pragma unroll
    for (int k = 0; k < 8; k++)
        #pragma unroll
        for (int j = 0; j < 16; j++)
            acc[j] = fmaf(a[k], sW[k * 16 + j], acc[j]);
    __half2 hv[8];
    #pragma unroll
    for (int v = 0; v < 8; v++)
        hv[v] = __floats2half2_rn(fmaxf(acc[2*v], 0.f) * io,
                                  fmaxf(acc[2*v+1], 0.f) * io);
    uint4* o = (uint4*)(g_h1s + (size_t)i * 8);
    o[0] = *(uint4*)(hv);
    o[1] = *(uint4*)(hv + 4);
}

// Layer 2+3a: acc16 = sum h1s[src] (fp16->fp32); h2 = relu(acc*ii @ W2 + b2);
//             z3 = (h2*io) @ W3 -> fp16 (10 vals, stride 8 half2)
__global__ void k_layer2(const float* __restrict__ W2, const float* __restrict__ b2,
                         const float* __restrict__ W3) {
    __shared__ float sW2[16 * 32];
    __shared__ float sb2[32];
    __shared__ float sW3[32 * 10];
    int t = threadIdx.x;
    for (int j = t; j < 16 * 32; j += blockDim.x) sW2[j] = W2[j];
    for (int j = t; j < 32 * 10; j += blockDim.x) sW3[j] = W3[j];
    if (t < 32) sb2[t] = b2[t];
    __syncthreads();
    int i = blockIdx.x * blockDim.x + t;
    if (i >= N_NODES) return;
    int beg = g_rowptr[i];
    int end = beg + g_degin[i];
    float a[16];
    #pragma unroll
    for (int j = 0; j < 16; j++) a[j] = 0.f;
    int e = beg;
    for (; e + 2 <= end; e += 2) {
        int s0 = g_csr_src[e], s1 = g_csr_src[e + 1];
        const uint4* p0 = (const uint4*)(g_h1s + (size_t)s0 * 8);
        const uint4* p1 = (const uint4*)(g_h1s + (size_t)s1 * 8);
        uint4 u0 = p0[0], v0 = p0[1];
        uint4 u1 = p1[0], v1 = p1[1];
        acc_h2(a[0],  a[1],  u0.x); acc_h2(a[2],  a[3],  u0.y);
        acc_h2(a[4],  a[5],  u0.z); acc_h2(a[6],  a[7],  u0.w);
        acc_h2(a[8],  a[9],  v0.x); acc_h2(a[10], a[11], v0.y);
        acc_h2(a[12], a[13], v0.z); acc_h2(a[14], a[15], v0.w);
        acc_h2(a[0],  a[1],  u1.x); acc_h2(a[2],  a[3],  u1.y);
        acc_h2(a[4],  a[5],  u1.z); acc_h2(a[6],  a[7],  u1.w);
        acc_h2(a[8],  a[9],  v1.x); acc_h2(a[10], a[11], v1.y);
        acc_h2(a[12], a[13], v1.z); acc_h2(a[14], a[15], v1.w);
    }
    for (; e < end; e++) {
        int s = g_csr_src[e];
        const uint4* p = (const uint4*)(g_h1s + (size_t)s * 8);
        uint4 u = p[0], v = p[1];
        acc_h2(a[0],  a[1],  u.x); acc_h2(a[2],  a[3],  u.y);
        acc_h2(a[4],  a[5],  u.z); acc_h2(a[6],  a[7],  u.w);
        acc_h2(a[8],  a[9],  v.x); acc_h2(a[10], a[11], v.y);
        acc_h2(a[12], a[13], v.z); acc_h2(a[14], a[15], v.w);
    }
    float ii = g_invin[i], io = g_invout[i];
    float acc[32];
    #pragma unroll
    for (int j = 0; j < 32; j++) acc[j] = sb2[j];
    #pragma unroll
    for (int k = 0; k < 16; k++) {
        float ak = a[k] * ii;
        #pragma unroll
        for (int j = 0; j < 32; j++)
            acc[j] = fmaf(ak, sW2[k * 32 + j], acc[j]);
    }
    float z[10];
    #pragma unroll
    for (int j = 0; j < 10; j++) z[j] = 0.f;
    #pragma unroll
    for (int k = 0; k < 32; k++) {
        float h = fmaxf(acc[k], 0.f) * io;
        #pragma unroll
        for (int j = 0; j < 10; j++)
            z[j] = fmaf(h, sW3[k * 10 + j], z[j]);
    }
    __half2 hv[5];
    #pragma unroll
    for (int v = 0; v < 5; v++)
        hv[v] = __floats2half2_rn(z[2*v], z[2*v+1]);
    __half2* o = g_z3h + (size_t)i * 8;
    *(uint4*)(o) = *(uint4*)(hv);
    *(unsigned*)(o + 4) = *(unsigned*)(hv + 4);
}

// Layer 3b + pool: node out = (sum z3[src]) * ii; per-graph sums in shared mem
__global__ void k_layer3(const int* __restrict__ gids) {
    __shared__ float ssum[N_GRAPHS * 10];
    int t = threadIdx.x;
    for (int j = t; j < N_GRAPHS * 10; j += blockDim.x) ssum[j] = 0.f;
    __syncthreads();
    int i = blockIdx.x * blockDim.x + t;
    float v[10];
    int g = -1;
    if (i < N_NODES) {
        #pragma unroll
        for (int j = 0; j < 10; j++) v[j] = 0.f;
        int beg = g_rowptr[i];
        int end = beg + g_degin[i];
        int e = beg;
        for (; e + 2 <= end; e += 2) {
            int s0 = g_csr_src[e], s1 = g_csr_src[e + 1];
            const __half2* r0 = g_z3h + (size_t)s0 * 8;
            const __half2* r1 = g_z3h + (size_t)s1 * 8;
            uint4 u0 = *(const uint4*)r0;
            unsigned w0 = *(const unsigned*)(r0 + 4);
            uint4 u1 = *(const uint4*)r1;
            unsigned w1 = *(const unsigned*)(r1 + 4);
            acc_h2(v[0], v[1], u0.x); acc_h2(v[2], v[3], u0.y);
            acc_h2(v[4], v[5], u0.z); acc_h2(v[6], v[7], u0.w);
            acc_h2(v[8], v[9], w0);
            acc_h2(v[0], v[1], u1.x); acc_h2(v[2], v[3], u1.y);
            acc_h2(v[4], v[5], u1.z); acc_h2(v[6], v[7], u1.w);
            acc_h2(v[8], v[9], w1);
        }
        for (; e < end; e++) {
            int s = g_csr_src[e];
            const __half2* r = g_z3h + (size_t)s * 8;
            uint4 u = *(const uint4*)r;
            unsigned w = *(const unsigned*)(r + 4);
            acc_h2(v[0], v[1], u.x); acc_h2(v[2], v[3], u.y);
            acc_h2(v[4], v[5], u.z); acc_h2(v[6], v[7], u.w);
            acc_h2(v[8], v[9], w);
        }
        float ii = g_invin[i];
        #pragma unroll
        for (int j = 0; j < 10; j++) v[j] *= ii;
        g = gids[i];
    } else {
        #pragma unroll
        for (int j = 0; j < 10; j++) v[j] = 0.f;
    }
    // warp-uniform graph id fast path (graph_ids are sorted)
    int leader = __shfl_sync(0xffffffffu, g, 0);
    bool uni = __all_sync(0xffffffffu, g == leader);
    if (uni && leader >= 0) {
        #pragma unroll
        for (int j = 0; j < 10; j++) {
            float s = v[j];
            #pragma unroll
            for (int off = 16; off > 0; off >>= 1)
                s += __shfl_xor_sync(0xffffffffu, s, off);
            if ((t & 31) == 0) atomicAdd(&ssum[leader * 10 + j], s);
        }
    } else if (g >= 0) {
        #pragma unroll
        for (int j = 0; j < 10; j++)
            atomicAdd(&ssum[g * 10 + j], v[j]);
    }
    __syncthreads();
    for (int j = t; j < N_GRAPHS * 10; j += blockDim.x) {
        float s = ssum[j];
        if (s != 0.f) atomicAdd(&g_gsum[j], s);
    }
}

__device__ __forceinline__ int lowerb(const int* __restrict__ a, int n, int v) {
    int lo = 0, hi = n;
    while (lo < hi) {
        int m = (lo + hi) >> 1;
        if (a[m] < v) lo = m + 1; else hi = m;
    }
    return lo;
}

__global__ void k_final(const int* __restrict__ gids, const float* __restrict__ b3,
                        float* __restrict__ out) {
    int i = blockIdx.x * blockDim.x + threadIdx.x;
    if (i >= N_GRAPHS * 10) return;
    int g = i / 10, j = i % 10;
    int lo = lowerb(gids, N_NODES, g);
    int hi = lowerb(gids, N_NODES, g + 1);
    float cnt = (float)(hi - lo);
    out[i] = g_gsum[i] / fmaxf(cnt, 1.f) + b3[j];
}

// ---------------- launch ------------------------------------------------------
extern "C" void kernel_launch(void* const* d_in, const int* in_sizes, int n_in,
                              void* d_out, int out_size) {
    const float* n_feat = (const float*)d_in[0];
    const int*   src    = (const int*)  d_in[1];
    const int*   dst    = (const int*)  d_in[2];
    const int*   gids   = (const int*)  d_in[3];
    const float* W1     = (const float*)d_in[4];
    const float* b1     = (const float*)d_in[5];
    const float* W2     = (const float*)d_in[6];
    const float* b2     = (const float*)d_in[7];
    const float* W3     = (const float*)d_in[8];
    const float* b3     = (const float*)d_in[9];
    float* out = (float*)d_out;

    const int TB = 256;
    const int nb  = (N_NODES + TB - 1) / TB;
    const int eb4 = (N_EDGES / 4 + TB - 1) / TB;
    const int eb2 = (N_EDGES / 2 + TB - 1) / TB;
    const int pb  = (N_NODES + 1023) / 1024;

    k_zero   <<<nb, TB>>>();
    k_degree <<<eb4, TB>>>(src, dst);
    k_prep   <<<nb, TB>>>(n_feat);
    k_fill   <<<eb2, TB>>>(src, dst);
    k_layer1 <<<nb, TB>>>(W1, b1);
    k_layer2 <<<nb, TB>>>(W2, b2, W3);
    k_layer3 <<<pb, 1024>>>(gids);
    k_final  <<<1, N_GRAPHS * 10>>>(gids, b3, out);
}

// round 5
// speedup vs baseline: 1.7667x; 1.1371x over previous
#include <cuda_runtime.h>
#include <cuda_fp16.h>

#define N_NODES  100000
#define N_EDGES  1600000
#define N_GRAPHS 64
#define ELL_W    64          // max in-degree pad (P(deg>64) ~ 1e-20)

// ---------------- scratch (device globals) ----------------------------------
__device__ __align__(256) __half2 g_x1h  [N_NODES * 4];   // n_feat*invout, fp16 (8 vals)
__device__ __align__(256) __half2 g_h1s  [N_NODES * 8];   // relu(h1)*invout, fp16 (16 vals)
__device__ __align__(256) __half2 g_z3h  [N_NODES * 8];   // (h2*invout)@W3, fp16 (10 vals)
__device__ __align__(256) float   g_invin [N_NODES];
__device__ __align__(256) float   g_invout[N_NODES];
__device__ __align__(256) int     g_degout[N_NODES];
__device__ __align__(256) int     g_degin [N_NODES];
__device__ __align__(256) int     g_ell   [(size_t)N_NODES * ELL_W];  // 25.6 MB
__device__ __align__(256) float   g_gsum [N_GRAPHS * 10];

__device__ __forceinline__ void acc_h2(float& a0, float& a1, unsigned bits) {
    __half2 h = *reinterpret_cast<__half2*>(&bits);
    float2 f = __half22float2(h);
    a0 += f.x; a1 += f.y;
}

// ---------------- build ------------------------------------------------------

__global__ void k_zero() {
    int i = blockIdx.x * blockDim.x + threadIdx.x;
    if (i < N_NODES) { g_degout[i] = 0; g_degin[i] = 0; }
    if (i < N_GRAPHS * 10) g_gsum[i] = 0.f;
}

// ONE edge pass: degree count + ELL fill (atomic return = slot index)
__global__ void k_fill(const int* __restrict__ src, const int* __restrict__ dst) {
    int t = blockIdx.x * blockDim.x + threadIdx.x;
    int base = t * 4;
    if (base >= N_EDGES) return;
    int4 s = *(const int4*)(src + base);
    int4 d = *(const int4*)(dst + base);
    atomicAdd(&g_degout[s.x], 1);
    atomicAdd(&g_degout[s.y], 1);
    atomicAdd(&g_degout[s.z], 1);
    atomicAdd(&g_degout[s.w], 1);
    int p0 = atomicAdd(&g_degin[d.x], 1);
    int p1 = atomicAdd(&g_degin[d.y], 1);
    int p2 = atomicAdd(&g_degin[d.z], 1);
    int p3 = atomicAdd(&g_degin[d.w], 1);
    g_ell[(size_t)d.x * ELL_W + p0] = s.x;
    g_ell[(size_t)d.y * ELL_W + p1] = s.y;
    g_ell[(size_t)d.z * ELL_W + p2] = s.z;
    g_ell[(size_t)d.w * ELL_W + p3] = s.w;
}

// inv-sqrt degrees + pre-scale node features by inv_sqrt_out -> fp16
__global__ void k_prep(const float* __restrict__ n_feat) {
    int i = blockIdx.x * blockDim.x + threadIdx.x;
    if (i >= N_NODES) return;
    float io = rsqrtf(fmaxf((float)g_degout[i], 1.f));
    float ii = rsqrtf(fmaxf((float)g_degin [i], 1.f));
    g_invin[i]  = ii;
    g_invout[i] = io;
    const float4* xr = (const float4*)(n_feat + (size_t)i * 8);
    float4 a = xr[0], b = xr[1];
    __half2 hv[4];
    hv[0] = __floats2half2_rn(a.x * io, a.y * io);
    hv[1] = __floats2half2_rn(a.z * io, a.w * io);
    hv[2] = __floats2half2_rn(b.x * io, b.y * io);
    hv[3] = __floats2half2_rn(b.z * io, b.w * io);
    *(uint4*)(g_x1h + (size_t)i * 4) = *(uint4*)hv;
}

// ---------------- fused gather + dense layers --------------------------------

// Layer 1: acc8 = sum x1h[src] (fp16->fp32); h1s = relu(acc*ii @ W1 + b1)*io -> fp16
__global__ void k_layer1(const float* __restrict__ W1, const float* __restrict__ b1) {
    __shared__ float sW[8 * 16];
    __shared__ float sb[16];
    int t = threadIdx.x;
    if (t < 128) sW[t] = W1[t];
    if (t < 16)  sb[t] = b1[t];
    __syncthreads();
    int i = blockIdx.x * blockDim.x + t;
    if (i >= N_NODES) return;
    int deg = g_degin[i];
    const int* row = g_ell + (size_t)i * ELL_W;
    float a[8];
    #pragma unroll
    for (int j = 0; j < 8; j++) a[j] = 0.f;
    int e = 0;
    for (; e + 4 <= deg; e += 4) {
        int4 s = *(const int4*)(row + e);                 // aligned
        uint4 u0 = *(const uint4*)(g_x1h + (size_t)s.x * 4);
        uint4 u1 = *(const uint4*)(g_x1h + (size_t)s.y * 4);
        uint4 u2 = *(const uint4*)(g_x1h + (size_t)s.z * 4);
        uint4 u3 = *(const uint4*)(g_x1h + (size_t)s.w * 4);
        acc_h2(a[0], a[1], u0.x); acc_h2(a[2], a[3], u0.y);
        acc_h2(a[4], a[5], u0.z); acc_h2(a[6], a[7], u0.w);
        acc_h2(a[0], a[1], u1.x); acc_h2(a[2], a[3], u1.y);
        acc_h2(a[4], a[5], u1.z); acc_h2(a[6], a[7], u1.w);
        acc_h2(a[0], a[1], u2.x); acc_h2(a[2], a[3], u2.y);
        acc_h2(a[4], a[5], u2.z); acc_h2(a[6], a[7], u2.w);
        acc_h2(a[0], a[1], u3.x); acc_h2(a[2], a[3], u3.y);
        acc_h2(a[4], a[5], u3.z); acc_h2(a[6], a[7], u3.w);
    }
    for (; e < deg; e++) {
        int s = row[e];
        uint4 u = *(const uint4*)(g_x1h + (size_t)s * 4);
        acc_h2(a[0], a[1], u.x); acc_h2(a[2], a[3], u.y);
        acc_h2(a[4], a[5], u.z); acc_h2(a[6], a[7], u.w);
    }
    float ii = g_invin[i], io = g_invout[i];
    float acc[16];
    #pragma unroll
    for (int j = 0; j < 16; j++) acc[j] = sb[j];
    #pragma unroll
    for (int k = 0; k < 8; k++) {
        float ak = a[k] * ii;
        #pragma unroll
        for (int j = 0; j < 16; j++)
            acc[j] = fmaf(ak, sW[k * 16 + j], acc[j]);
    }
    __half2 hv[8];
    #pragma unroll
    for (int v = 0; v < 8; v++)
        hv[v] = __floats2half2_rn(fmaxf(acc[2*v], 0.f) * io,
                                  fmaxf(acc[2*v+1], 0.f) * io);
    uint4* o = (uint4*)(g_h1s + (size_t)i * 8);
    o[0] = *(uint4*)(hv);
    o[1] = *(uint4*)(hv + 4);
}

// Layer 2+3a: acc16 = sum h1s[src]; h2 = relu(acc*ii @ W2 + b2);
//             z3 = (h2*io) @ W3 -> fp16
__global__ void k_layer2(const float* __restrict__ W2, const float* __restrict__ b2,
                         const float* __restrict__ W3) {
    __shared__ float sW2[16 * 32];
    __shared__ float sb2[32];
    __shared__ float sW3[32 * 10];
    int t = threadIdx.x;
    for (int j = t; j < 16 * 32; j += blockDim.x) sW2[j] = W2[j];
    for (int j = t; j < 32 * 10; j += blockDim.x) sW3[j] = W3[j];
    if (t < 32) sb2[t] = b2[t];
    __syncthreads();
    int i = blockIdx.x * blockDim.x + t;
    if (i >= N_NODES) return;
    int deg = g_degin[i];
    const int* row = g_ell + (size_t)i * ELL_W;
    float a[16];
    #pragma unroll
    for (int j = 0; j < 16; j++) a[j] = 0.f;
    int e = 0;
    for (; e + 2 <= deg; e += 2) {
        int s0 = row[e], s1 = row[e + 1];
        const uint4* p0 = (const uint4*)(g_h1s + (size_t)s0 * 8);
        const uint4* p1 = (const uint4*)(g_h1s + (size_t)s1 * 8);
        uint4 u0 = p0[0], v0 = p0[1];
        uint4 u1 = p1[0], v1 = p1[1];
        acc_h2(a[0],  a[1],  u0.x); acc_h2(a[2],  a[3],  u0.y);
        acc_h2(a[4],  a[5],  u0.z); acc_h2(a[6],  a[7],  u0.w);
        acc_h2(a[8],  a[9],  v0.x); acc_h2(a[10], a[11], v0.y);
        acc_h2(a[12], a[13], v0.z); acc_h2(a[14], a[15], v0.w);
        acc_h2(a[0],  a[1],  u1.x); acc_h2(a[2],  a[3],  u1.y);
        acc_h2(a[4],  a[5],  u1.z); acc_h2(a[6],  a[7],  u1.w);
        acc_h2(a[8],  a[9],  v1.x); acc_h2(a[10], a[11], v1.y);
        acc_h2(a[12], a[13], v1.z); acc_h2(a[14], a[15], v1.w);
    }
    for (; e < deg; e++) {
        int s = row[e];
        const uint4* p = (const uint4*)(g_h1s + (size_t)s * 8);
        uint4 u = p[0], v = p[1];
        acc_h2(a[0],  a[1],  u.x); acc_h2(a[2],  a[3],  u.y);
        acc_h2(a[4],  a[5],  u.z); acc_h2(a[6],  a[7],  u.w);
        acc_h2(a[8],  a[9],  v.x); acc_h2(a[10], a[11], v.y);
        acc_h2(a[12], a[13], v.z); acc_h2(a[14], a[15], v.w);
    }
    float ii = g_invin[i], io = g_invout[i];
    float acc[32];
    #pragma unroll
    for (int j = 0; j < 32; j++) acc[j] = sb2[j];
    #pragma unroll
    for (int k = 0; k < 16; k++) {
        float ak = a[k] * ii;
        #pragma unroll
        for (int j = 0; j < 32; j++)
            acc[j] = fmaf(ak, sW2[k * 32 + j], acc[j]);
    }
    float z[10];
    #pragma unroll
    for (int j = 0; j < 10; j++) z[j] = 0.f;
    #pragma unroll
    for (int k = 0; k < 32; k++) {
        float h = fmaxf(acc[k], 0.f) * io;
        #pragma unroll
        for (int j = 0; j < 10; j++)
            z[j] = fmaf(h, sW3[k * 10 + j], z[j]);
    }
    __half2 hv[5];
    #pragma unroll
    for (int v = 0; v < 5; v++)
        hv[v] = __floats2half2_rn(z[2*v], z[2*v+1]);
    __half2* o = g_z3h + (size_t)i * 8;
    *(uint4*)(o) = *(uint4*)(hv);
    *(unsigned*)(o + 4) = *(unsigned*)(hv + 4);
}

// Layer 3b + pool
__global__ void k_layer3(const int* __restrict__ gids) {
    __shared__ float ssum[N_GRAPHS * 10];
    int t = threadIdx.x;
    for (int j = t; j < N_GRAPHS * 10; j += blockDim.x) ssum[j] = 0.f;
    __syncthreads();
    int i = blockIdx.x * blockDim.x + t;
    float v[10];
    int g = -1;
    if (i < N_NODES) {
        #pragma unroll
        for (int j = 0; j < 10; j++) v[j] = 0.f;
        int deg = g_degin[i];
        const int* row = g_ell + (size_t)i * ELL_W;
        int e = 0;
        for (; e + 2 <= deg; e += 2) {
            int s0 = row[e], s1 = row[e + 1];
            const __half2* r0 = g_z3h + (size_t)s0 * 8;
            const __half2* r1 = g_z3h + (size_t)s1 * 8;
            uint4 u0 = *(const uint4*)r0;
            unsigned w0 = *(const unsigned*)(r0 + 4);
            uint4 u1 = *(const uint4*)r1;
            unsigned w1 = *(const unsigned*)(r1 + 4);
            acc_h2(v[0], v[1], u0.x); acc_h2(v[2], v[3], u0.y);
            acc_h2(v[4], v[5], u0.z); acc_h2(v[6], v[7], u0.w);
            acc_h2(v[8], v[9], w0);
            acc_h2(v[0], v[1], u1.x); acc_h2(v[2], v[3], u1.y);
            acc_h2(v[4], v[5], u1.z); acc_h2(v[6], v[7], u1.w);
            acc_h2(v[8], v[9], w1);
        }
        for (; e < deg; e++) {
            int s = row[e];
            const __half2* r = g_z3h + (size_t)s * 8;
            uint4 u = *(const uint4*)r;
            unsigned w = *(const unsigned*)(r + 4);
            acc_h2(v[0], v[1], u.x); acc_h2(v[2], v[3], u.y);
            acc_h2(v[4], v[5], u.z); acc_h2(v[6], v[7], u.w);
            acc_h2(v[8], v[9], w);
        }
        float ii = g_invin[i];
        #pragma unroll
        for (int j = 0; j < 10; j++) v[j] *= ii;
        g = gids[i];
    } else {
        #pragma unroll
        for (int j = 0; j < 10; j++) v[j] = 0.f;
    }
    int leader = __shfl_sync(0xffffffffu, g, 0);
    bool uni = __all_sync(0xffffffffu, g == leader);
    if (uni && leader >= 0) {
        #pragma unroll
        for (int j = 0; j < 10; j++) {
            float s = v[j];
            #pragma unroll
            for (int off = 16; off > 0; off >>= 1)
                s += __shfl_xor_sync(0xffffffffu, s, off);
            if ((t & 31) == 0) atomicAdd(&ssum[leader * 10 + j], s);
        }
    } else if (g >= 0) {
        #pragma unroll
        for (int j = 0; j < 10; j++)
            atomicAdd(&ssum[g * 10 + j], v[j]);
    }
    __syncthreads();
    for (int j = t; j < N_GRAPHS * 10; j += blockDim.x) {
        float s = ssum[j];
        if (s != 0.f) atomicAdd(&g_gsum[j], s);
    }
}

__device__ __forceinline__ int lowerb(const int* __restrict__ a, int n, int v) {
    int lo = 0, hi = n;
    while (lo < hi) {
        int m = (lo + hi) >> 1;
        if (a[m] < v) lo = m + 1; else hi = m;
    }
    return lo;
}

__global__ void k_final(const int* __restrict__ gids, const float* __restrict__ b3,
                        float* __restrict__ out) {
    int i = blockIdx.x * blockDim.x + threadIdx.x;
    if (i >= N_GRAPHS * 10) return;
    int g = i / 10, j = i % 10;
    int lo = lowerb(gids, N_NODES, g);
    int hi = lowerb(gids, N_NODES, g + 1);
    float cnt = (float)(hi - lo);
    out[i] = g_gsum[i] / fmaxf(cnt, 1.f) + b3[j];
}

// ---------------- launch ------------------------------------------------------
extern "C" void kernel_launch(void* const* d_in, const int* in_sizes, int n_in,
                              void* d_out, int out_size) {
    const float* n_feat = (const float*)d_in[0];
    const int*   src    = (const int*)  d_in[1];
    const int*   dst    = (const int*)  d_in[2];
    const int*   gids   = (const int*)  d_in[3];
    const float* W1     = (const float*)d_in[4];
    const float* b1     = (const float*)d_in[5];
    const float* W2     = (const float*)d_in[6];
    const float* b2     = (const float*)d_in[7];
    const float* W3     = (const float*)d_in[8];
    const float* b3     = (const float*)d_in[9];
    float* out = (float*)d_out;

    const int TB = 256;
    const int nb  = (N_NODES + TB - 1) / TB;
    const int eb4 = (N_EDGES / 4 + TB - 1) / TB;
    const int pb  = (N_NODES + 1023) / 1024;

    k_zero   <<<nb, TB>>>();
    k_fill   <<<eb4, TB>>>(src, dst);
    k_prep   <<<nb, TB>>>(n_feat);
    k_layer1 <<<nb, TB>>>(W1, b1);
    k_layer2 <<<nb, TB>>>(W2, b2, W3);
    k_layer3 <<<pb, 1024>>>(gids);
    k_final  <<<1, N_GRAPHS * 10>>>(gids, b3, out);
}